// round 8
// baseline (speedup 1.0000x reference)
#include <cuda_runtime.h>
#include <cuda_bf16.h>
#include <math.h>
#include <stdint.h>

// Model dims: B=64,T=512,F=161,V=32,L=64,H=128,E=32
// conv1: (64,1,512,161)->(64,32,241,80)  conv2: ->(64,32,105,36) -> (64,105,1152)
#define NB 64
#define C1H 241
#define C1W 80
#define C2H 105

typedef unsigned long long ull;

// ---------------- device scratch ----------------
__device__ float g_conv1[NB * 32 * C1H * C1W];
__device__ float g_conv2[NB * C2H * 1152];
__device__ float g_xp   [NB * C2H * 384];
__device__ float g_eh   [NB * C2H * 128];
__device__ float g_embA [NB * 63 * 32];
__device__ float g_ip   [NB * 63 * 384];
__device__ float g_ctxs [NB * 63 * 128];
__device__ float g_wT   [128 * 384];
// conv2 weights split hi/lo bf16: 64 tiles [(kh,half)] x [32 co][200 k-padded]
__device__ __nv_bfloat16 g_w2hi[64 * 32 * 200];
__device__ __nv_bfloat16 g_w2lo[64 * 32 * 200];

// ---------------- helpers ----------------
__device__ __forceinline__ uint32_t smem_u32(const void* p) {
    uint32_t a;
    asm("{ .reg .u64 t; cvta.to.shared.u64 t, %1; cvt.u32.u64 %0, t; }" : "=r"(a) : "l"(p));
    return a;
}
__device__ __forceinline__ void ldsm4(uint32_t* d, uint32_t addr) {
    asm volatile("ldmatrix.sync.aligned.m8n8.x4.shared.b16 {%0,%1,%2,%3}, [%4];"
                 : "=r"(d[0]), "=r"(d[1]), "=r"(d[2]), "=r"(d[3]) : "r"(addr));
}
__device__ __forceinline__ void mma_bf16(float* c, const uint32_t* a,
                                         uint32_t b0, uint32_t b1) {
    asm volatile(
        "mma.sync.aligned.m16n8k16.row.col.f32.bf16.bf16.f32 "
        "{%0,%1,%2,%3}, {%4,%5,%6,%7}, {%8,%9}, {%0,%1,%2,%3};"
        : "+f"(c[0]), "+f"(c[1]), "+f"(c[2]), "+f"(c[3])
        : "r"(a[0]), "r"(a[1]), "r"(a[2]), "r"(a[3]), "r"(b0), "r"(b1));
}
__device__ __forceinline__ uint32_t pack_bf2(float x, float y) {
    __nv_bfloat16 h0 = __float2bfloat16(x), h1 = __float2bfloat16(y);
    return ((uint32_t)__bfloat16_as_ushort(h1) << 16) | (uint32_t)__bfloat16_as_ushort(h0);
}

// ---------------- conv1: normalize + conv + relu ----------------
__global__ void conv1_kernel(const float* __restrict__ x,
                             const float* __restrict__ mean,
                             const float* __restrict__ stdv,
                             const float* __restrict__ w,
                             const float* __restrict__ bias) {
    int oh = blockIdx.x, b = blockIdx.y;
    __shared__ float s_x[32 * 161];
    __shared__ float s_w[2048];
    int tid = threadIdx.x;
    for (int i = tid; i < 32 * 161; i += 256) {
        int kh = i / 161, iw = i % 161;
        int ih = 2 * oh + kh;
        s_x[i] = (x[(b * 512 + ih) * 161 + iw] - mean[iw]) / stdv[iw];
    }
    for (int i = tid; i < 2048; i += 256) s_w[i] = w[i];
    __syncthreads();

    int c = tid >> 3, owb = tid & 7;
    float acc[10];
#pragma unroll
    for (int j = 0; j < 10; j++) acc[j] = 0.f;
    for (int kh = 0; kh < 32; kh++) {
        float w0 = s_w[c * 64 + kh * 2], w1 = s_w[c * 64 + kh * 2 + 1];
        const float* xr = &s_x[kh * 161];
#pragma unroll
        for (int j = 0; j < 10; j++) {
            int ow = owb + 8 * j;
            acc[j] += w0 * xr[2 * ow] + w1 * xr[2 * ow + 1];
        }
    }
    float bb = bias[c];
#pragma unroll
    for (int j = 0; j < 10; j++) {
        int ow = owb + 8 * j;
        float v = acc[j] + bb;
        g_conv1[((size_t)(b * 32 + c) * C1H + oh) * C1W + ow] = v > 0.f ? v : 0.f;
    }
}

// -------- prep conv2 weights: split hi/lo bf16, [kh*2+half][co][cil*12+kw] --
__global__ void prep_w2(const float* __restrict__ w) {
    int i = blockIdx.x * 256 + threadIdx.x;
    if (i >= 32 * 2 * 32 * 16 * 12) return;
    int kw = i % 12; int t = i / 12;
    int cil = t & 15; t >>= 4;
    int co = t & 31; t >>= 5;
    int half = t & 1; int kh = t >> 1;
    int ci = half * 16 + cil;
    float val = (kw < 9) ? w[((co * 32 + ci) * 32 + kh) * 9 + kw] : 0.f;
    __nv_bfloat16 hi = __float2bfloat16(val);
    __nv_bfloat16 lo = __float2bfloat16(val - __bfloat162float(hi));
    int idx = ((kh * 2 + half) * 32 + co) * 200 + cil * 12 + kw;
    g_w2hi[idx] = hi;
    g_w2lo[idx] = lo;
}

// ---------------- conv2 via mma.sync bf16 hi/lo split -------------------------
// grid (35, 64), 384 threads. CTA = (b, 3 oh rows -> M=128 padded), N=32 co.
// 64 iters (kh,half): stage A hi/lo patches (128x192, stride 200 bf16) + B tiles,
// warps 0-7 do m16n8k16 mma (16 rows each, 4 ntiles, 12 ksteps, 3 products).
#define KS 200   // padded k stride (bf16 elems); 400B: ldmatrix conflict-free
__global__ void __launch_bounds__(384, 1) conv2_mma_kernel(const float* __restrict__ bias) {
    extern __shared__ __align__(16) char base[];
    const int OFF_AHI = 0, OFF_ALO = 51200, OFF_BHI = 102400, OFF_BLO = 115200;
    uint32_t sb = smem_u32(base);
    int tid = threadIdx.x, wid = tid >> 5, lane = tid & 31;
    int oh0 = blockIdx.x * 3, b = blockIdx.y;
    const float* srcb = g_conv1 + (size_t)b * 32 * C1H * C1W;

    float acc[4][4];
#pragma unroll
    for (int i = 0; i < 4; i++)
#pragma unroll
        for (int j = 0; j < 4; j++) acc[i][j] = 0.f;

    // ldmatrix per-lane address components
    int r = lane & 7, q = lane >> 3;
    uint32_t a_row = (uint32_t)(16 * wid + (q & 1) * 8 + r) * 400 + (uint32_t)((q >> 1) * 8) * 2;
    uint32_t b_row = (uint32_t)((q >> 1) * 8 + r) * 400 + (uint32_t)((q & 1) * 8) * 2;

    for (int kh = 0; kh < 32; kh++) {
#pragma unroll 1
        for (int half = 0; half < 2; half++) {
            // B tiles: straight copy (global layout == smem layout, stride 200)
            {
                const uint4* wh = (const uint4*)(g_w2hi + (size_t)(kh * 2 + half) * 6400);
                const uint4* wl = (const uint4*)(g_w2lo + (size_t)(kh * 2 + half) * 6400);
                uint4* dh = (uint4*)(base + OFF_BHI);
                uint4* dl = (uint4*)(base + OFF_BLO);
                for (int i = tid; i < 800; i += 384) { dh[i] = wh[i]; dl[i] = wl[i]; }
            }
            // A patches: 128 rows x 16 cil x 6 kw-pairs (p=5 zero pad)
            for (int idx = tid; idx < 12288; idx += 384) {
                int p = idx % 6; int t2 = idx / 6;
                int cil = t2 & 15; int row = t2 >> 4;
                int rr = row < 108 ? row : 107;
                int ohi = rr / 36, ow = rr - 36 * ohi;
                int ih = 2 * (oh0 + ohi) + kh;
                int ci = half * 16 + cil;
                float vx = 0.f, vy = 0.f;
                if (p < 5) {
                    float2 v = *(const float2*)(srcb + ((size_t)ci * C1H + ih) * C1W
                                                + 2 * ow + 2 * p);
                    vx = v.x; vy = v.y;
                }
                __nv_bfloat16 h0 = __float2bfloat16(vx), h1 = __float2bfloat16(vy);
                float l0 = vx - __bfloat162float(h0), l1 = vy - __bfloat162float(h1);
                uint32_t ph = ((uint32_t)__bfloat16_as_ushort(h1) << 16)
                            | (uint32_t)__bfloat16_as_ushort(h0);
                uint32_t pl = pack_bf2(l0, l1);
                int boff = row * 400 + (cil * 12 + 2 * p) * 2;
                *(uint32_t*)(base + OFF_AHI + boff) = ph;
                *(uint32_t*)(base + OFF_ALO + boff) = pl;
            }
            __syncthreads();

            if (wid < 8) {
#pragma unroll 2
                for (int k = 0; k < 12; k++) {
                    uint32_t ka = (uint32_t)k * 32;
                    uint32_t ah[4], al[4];
                    ldsm4(ah, sb + OFF_AHI + a_row + ka);
                    ldsm4(al, sb + OFF_ALO + a_row + ka);
#pragma unroll
                    for (int np = 0; np < 2; np++) {
                        uint32_t bh[4], bl[4];
                        uint32_t brow = b_row + (uint32_t)np * 6400;
                        ldsm4(bh, sb + OFF_BHI + brow + ka);
                        ldsm4(bl, sb + OFF_BLO + brow + ka);
                        mma_bf16(acc[2 * np],     ah, bh[0], bh[1]);
                        mma_bf16(acc[2 * np + 1], ah, bh[2], bh[3]);
                        mma_bf16(acc[2 * np],     ah, bl[0], bl[1]);
                        mma_bf16(acc[2 * np + 1], ah, bl[2], bl[3]);
                        mma_bf16(acc[2 * np],     al, bh[0], bh[1]);
                        mma_bf16(acc[2 * np + 1], al, bh[2], bh[3]);
                    }
                }
            }
            __syncthreads();
        }
    }

    // epilogue: fragment -> g_conv2 (b, t, co*36+ow), +bias, relu
    if (wid < 8) {
        int row0 = 16 * wid + (lane >> 2);
#pragma unroll
        for (int nt = 0; nt < 4; nt++) {
            int col = 8 * nt + (lane & 3) * 2;
            float b0 = bias[col], b1 = bias[col + 1];
#pragma unroll
            for (int h = 0; h < 2; h++) {
                int row = row0 + 8 * h;
                if (row < 108) {
                    int ohi = row / 36, ow = row - 36 * ohi;
                    float* dst = &g_conv2[((size_t)b * C2H + oh0 + ohi) * 1152 + ow];
                    float v0 = acc[nt][2 * h] + b0;
                    float v1 = acc[nt][2 * h + 1] + b1;
                    dst[col * 36] = v0 > 0.f ? v0 : 0.f;
                    dst[(col + 1) * 36] = v1 > 0.f ? v1 : 0.f;
                }
            }
        }
    }
}

// ---------------- generic C[M,N] = A[M,K] * B[N,K]^T + bias ----------------
__global__ void gemm_nt(const float* __restrict__ A, const float* __restrict__ Bm,
                        const float* __restrict__ bias, float* __restrict__ C,
                        int M, int N, int K) {
    __shared__ float sA[8][128];
    __shared__ float sB[8][128];
    int bm = blockIdx.y * 128, bn = blockIdx.x * 128;
    int tid = threadIdx.x;
    int ty = tid >> 4, tx = tid & 15;
    float acc[8][8];
#pragma unroll
    for (int i = 0; i < 8; i++)
#pragma unroll
        for (int j = 0; j < 8; j++) acc[i][j] = 0.f;

    int lrow = tid >> 1, lk = (tid & 1) * 4;
    for (int k0 = 0; k0 < K; k0 += 8) {
        float4 av = make_float4(0.f, 0.f, 0.f, 0.f);
        float4 bv = make_float4(0.f, 0.f, 0.f, 0.f);
        if (bm + lrow < M) av = *(const float4*)&A[(size_t)(bm + lrow) * K + k0 + lk];
        if (bn + lrow < N) bv = *(const float4*)&Bm[(size_t)(bn + lrow) * K + k0 + lk];
        sA[lk + 0][lrow] = av.x; sA[lk + 1][lrow] = av.y;
        sA[lk + 2][lrow] = av.z; sA[lk + 3][lrow] = av.w;
        sB[lk + 0][lrow] = bv.x; sB[lk + 1][lrow] = bv.y;
        sB[lk + 2][lrow] = bv.z; sB[lk + 3][lrow] = bv.w;
        __syncthreads();
#pragma unroll
        for (int k = 0; k < 8; k++) {
            float a[8], bb[8];
            *(float4*)&a[0] = *(const float4*)&sA[k][ty * 8];
            *(float4*)&a[4] = *(const float4*)&sA[k][ty * 8 + 4];
            *(float4*)&bb[0] = *(const float4*)&sB[k][tx * 8];
            *(float4*)&bb[4] = *(const float4*)&sB[k][tx * 8 + 4];
#pragma unroll
            for (int i = 0; i < 8; i++)
#pragma unroll
                for (int j = 0; j < 8; j++) acc[i][j] += a[i] * bb[j];
        }
        __syncthreads();
    }
    for (int i = 0; i < 8; i++) {
        int m = bm + ty * 8 + i;
        if (m >= M) break;
        for (int j = 0; j < 8; j++) {
            int n = bn + tx * 8 + j;
            if (n < N) C[(size_t)m * N + n] = acc[i][j] + bias[n];
        }
    }
}

// ---------------- encoder GRU: one block per batch element ----------------
__global__ void encoder_kernel(const float* __restrict__ w_hh,
                               const float* __restrict__ b_hh) {
    extern __shared__ float sm[];
    float* s_w = sm;              // 384*132 (padded stride)
    float* s_h = sm + 50688;
    float* s_gh = sm + 50816;
    int b = blockIdx.x, tid = threadIdx.x;
    for (int i = tid; i < 49152; i += 384) {
        int r = i >> 7, c = i & 127;
        s_w[r * 132 + c] = w_hh[i];
    }
    if (tid < 128) s_h[tid] = 0.f;
    __syncthreads();
    float bn = b_hh[tid];
    const float4* wr = (const float4*)&s_w[tid * 132];
    for (int t = 0; t < 105; t++) {
        float a0 = bn, a1 = 0.f;
#pragma unroll
        for (int k = 0; k < 16; k++) {
            float4 wv = wr[2 * k];
            float4 hv = ((const float4*)s_h)[2 * k];
            a0 += wv.x * hv.x + wv.y * hv.y + wv.z * hv.z + wv.w * hv.w;
            float4 wv2 = wr[2 * k + 1];
            float4 hv2 = ((const float4*)s_h)[2 * k + 1];
            a1 += wv2.x * hv2.x + wv2.y * hv2.y + wv2.z * hv2.z + wv2.w * hv2.w;
        }
        s_gh[tid] = a0 + a1;
        __syncthreads();
        if (tid < 128) {
            const float* xrow = &g_xp[((size_t)b * 105 + t) * 384];
            float r = 1.f / (1.f + __expf(-(xrow[tid] + s_gh[tid])));
            float z = 1.f / (1.f + __expf(-(xrow[128 + tid] + s_gh[128 + tid])));
            float nn = tanhf(xrow[256 + tid] + r * s_gh[256 + tid]);
            float hnew = (1.f - z) * nn + z * s_h[tid];
            s_h[tid] = hnew;
            g_eh[((size_t)b * 105 + t) * 128 + tid] = hnew;
        }
        __syncthreads();
    }
}

// ---------------- decoder: GRU step + attention, one block per batch ----------------
__device__ __forceinline__ float warpred_max(float v) {
#pragma unroll
    for (int o = 16; o; o >>= 1) v = fmaxf(v, __shfl_xor_sync(0xffffffffu, v, o));
    return v;
}
__device__ __forceinline__ float warpred_sum(float v) {
#pragma unroll
    for (int o = 16; o; o >>= 1) v += __shfl_xor_sync(0xffffffffu, v, o);
    return v;
}

__global__ void decoder_kernel(const float* __restrict__ b_hh) {
    extern __shared__ float sm[];
    float* s_eh = sm;              // 105*132
    float* s_h = sm + 13860;
    float* s_gh = sm + 13988;
    float* s_hx2 = sm + 14372;
    float* s_att = sm + 14500;
    float* s_red = sm + 14628;
    int b = blockIdx.x, tid = threadIdx.x;

    for (int i = tid; i < 13440; i += 384) {
        int t = i >> 7, k = i & 127;
        s_eh[t * 132 + k] = g_eh[(size_t)b * 105 * 128 + i];
    }
    if (tid < 128) s_h[tid] = 0.f;
    __syncthreads();

    float bn = b_hh[tid];
    for (int l = 0; l < 63; l++) {
        float a0 = bn, a1 = 0.f;
#pragma unroll 8
        for (int k = 0; k < 64; k++) {
            a0 += g_wT[k * 384 + tid] * s_h[k];
            a1 += g_wT[(k + 64) * 384 + tid] * s_h[k + 64];
        }
        s_gh[tid] = a0 + a1;
        __syncthreads();

        if (tid < 128) {
            const float* irow = &g_ip[((size_t)b * 63 + l) * 384];
            float r = 1.f / (1.f + __expf(-(irow[tid] + s_gh[tid])));
            float z = 1.f / (1.f + __expf(-(irow[128 + tid] + s_gh[128 + tid])));
            float nn = tanhf(irow[256 + tid] + r * s_gh[256 + tid]);
            s_hx2[tid] = (1.f - z) * nn + z * s_h[tid];
        }
        __syncthreads();

        float sc = -1e30f;
        if (tid < 105) {
            const float4* er = (const float4*)&s_eh[tid * 132];
            const float4* hx = (const float4*)s_hx2;
            float d = 0.f;
#pragma unroll 8
            for (int k = 0; k < 32; k++) {
                float4 e4 = er[k], h4 = hx[k];
                d += e4.x * h4.x + e4.y * h4.y + e4.z * h4.z + e4.w * h4.w;
            }
            sc = d;
        }
        float m = warpred_max(sc);
        if ((tid & 31) == 0) s_red[tid >> 5] = m;
        __syncthreads();
        if (tid < 32) {
            float wv = (tid < 12) ? s_red[tid] : -1e30f;
            wv = warpred_max(wv);
            if (tid == 0) s_red[12] = wv;
        }
        __syncthreads();
        float mx = s_red[12];
        float e = (tid < 105) ? __expf(sc - mx) : 0.f;
        float sv = warpred_sum(e);
        if ((tid & 31) == 0) s_red[16 + (tid >> 5)] = sv;
        if (tid < 128) s_att[tid] = e;
        __syncthreads();
        if (tid < 32) {
            float wv = (tid < 12) ? s_red[16 + tid] : 0.f;
            wv = warpred_sum(wv);
            if (tid == 0) s_red[13] = wv;
        }
        __syncthreads();
        float inv = 1.f / s_red[13];

        if (tid < 128) {
            float c = 0.f;
            for (int t = 0; t < 105; t++) c += s_att[t] * s_eh[t * 132 + tid];
            c *= inv;
            s_h[tid] = c;
            g_ctxs[((size_t)b * 63 + l) * 128 + tid] = c;
        }
        __syncthreads();
    }
}

// ---------------- small helpers ----------------
__global__ void emb_gather(const int* __restrict__ y, const float* __restrict__ emb) {
    int i = blockIdx.x * 256 + threadIdx.x;
    if (i >= NB * 63 * 32) return;
    int m = i >> 5, e = i & 31;
    int bb = m / 63, l = m % 63;
    int idx = y[bb * 64 + l];
    g_embA[i] = emb[idx * 32 + e];
}

__global__ void transpose_whh(const float* __restrict__ w) {
    int i = blockIdx.x * 256 + threadIdx.x;
    if (i < 49152) {
        int n = i >> 7, k = i & 127;
        g_wT[k * 384 + n] = w[i];
    }
}

// ---------------- launch ----------------
extern "C" void kernel_launch(void* const* d_in, const int* in_sizes, int n_in,
                              void* d_out, int out_size) {
    const float* x    = (const float*)d_in[0];
    const int*   y    = (const int*)d_in[1];
    const float* mean = (const float*)d_in[2];
    const float* stdv = (const float*)d_in[3];
    const float* c1w  = (const float*)d_in[4];
    const float* c1b  = (const float*)d_in[5];
    const float* c2w  = (const float*)d_in[6];
    const float* c2b  = (const float*)d_in[7];
    const float* gwih = (const float*)d_in[8];
    const float* gwhh = (const float*)d_in[9];
    const float* gbih = (const float*)d_in[10];
    const float* gbhh = (const float*)d_in[11];
    const float* emb  = (const float*)d_in[12];
    const float* dwih = (const float*)d_in[13];
    const float* dwhh = (const float*)d_in[14];
    const float* dbih = (const float*)d_in[15];
    const float* dbhh = (const float*)d_in[16];
    const float* fcw  = (const float*)d_in[17];
    const float* fcb  = (const float*)d_in[18];
    float* out = (float*)d_out;

    cudaFuncSetAttribute(encoder_kernel, cudaFuncAttributeMaxDynamicSharedMemorySize, 204800);
    cudaFuncSetAttribute(decoder_kernel, cudaFuncAttributeMaxDynamicSharedMemorySize, 58640);
    cudaFuncSetAttribute(conv2_mma_kernel, cudaFuncAttributeMaxDynamicSharedMemorySize, 128000);

    void *p_conv2, *p_xp, *p_embA, *p_ip, *p_ctxs;
    cudaGetSymbolAddress(&p_conv2, g_conv2);
    cudaGetSymbolAddress(&p_xp, g_xp);
    cudaGetSymbolAddress(&p_embA, g_embA);
    cudaGetSymbolAddress(&p_ip, g_ip);
    cudaGetSymbolAddress(&p_ctxs, g_ctxs);

    prep_w2<<<(32 * 2 * 32 * 16 * 12 + 255) / 256, 256>>>(c2w);
    transpose_whh<<<192, 256>>>(dwhh);
    conv1_kernel<<<dim3(C1H, NB), 256>>>(x, mean, stdv, c1w, c1b);
    conv2_mma_kernel<<<dim3(35, NB), 384, 128000>>>(c2b);
    // xp = conv_out @ gru_w_ih^T + gru_b_ih : (6720,1152)x(384,1152)
    gemm_nt<<<dim3(3, 53), 256>>>((const float*)p_conv2, gwih, gbih, (float*)p_xp,
                                  NB * C2H, 384, 1152);
    encoder_kernel<<<NB, 384, 204800>>>(gwhh, gbhh);

    emb_gather<<<(NB * 63 * 32 + 255) / 256, 256>>>(y, emb);
    // ip = emb_in @ dec_w_ih^T + dec_b_ih : (4032,32)x(384,32)
    gemm_nt<<<dim3(3, 32), 256>>>((const float*)p_embA, dwih, dbih, (float*)p_ip,
                                  NB * 63, 384, 32);
    decoder_kernel<<<NB, 384, 58640>>>(dbhh);
    // out = ctxs @ fc_w^T + fc_b : (4032,128)x(32,128)
    gemm_nt<<<dim3(1, 32), 256>>>((const float*)p_ctxs, fcw, fcb, out,
                                  NB * 63, 32, 128);
}

// round 11
// speedup vs baseline: 4.9781x; 4.9781x over previous
#include <cuda_runtime.h>
#include <cuda_bf16.h>
#include <math.h>
#include <stdint.h>

// Model dims: B=64,T=512,F=161,V=32,L=64,H=128,E=32
// conv1: (64,1,512,161)->(64,32,241,80)  conv2: ->(64,32,105,36) -> (64,105,1152)
#define NB 64
#define C1H 241
#define C1W 80
#define C2H 105

typedef unsigned long long ull;

// ---------------- device scratch ----------------
// conv1 output as bf16 hi/lo, layout [b][ih][iw][ci]
__device__ __nv_bfloat16 g_c1h[NB * C1H * C1W * 32];
__device__ __nv_bfloat16 g_c1l[NB * C1H * C1W * 32];
__device__ float g_conv2[NB * C2H * 1152];
__device__ float g_xp   [NB * C2H * 384];
__device__ float g_eh   [NB * C2H * 128];
__device__ float g_embA [NB * 63 * 32];
__device__ float g_ip   [NB * 63 * 384];
__device__ float g_ctxs [NB * 63 * 128];
__device__ float g_wT   [128 * 384];
// conv2 weights hi/lo: [kh][kw][co][ci]  (32*9*32*32)
__device__ __nv_bfloat16 g_w2h[294912];
__device__ __nv_bfloat16 g_w2l[294912];

// ---------------- helpers ----------------
__device__ __forceinline__ uint32_t smem_u32(const void* p) {
    uint32_t a;
    asm("{ .reg .u64 t; cvta.to.shared.u64 t, %1; cvt.u32.u64 %0, t; }" : "=r"(a) : "l"(p));
    return a;
}
__device__ __forceinline__ void ldsm4(uint32_t* d, uint32_t addr) {
    asm volatile("ldmatrix.sync.aligned.m8n8.x4.shared.b16 {%0,%1,%2,%3}, [%4];"
                 : "=r"(d[0]), "=r"(d[1]), "=r"(d[2]), "=r"(d[3]) : "r"(addr));
}
__device__ __forceinline__ void mma_bf16(float* c, const uint32_t* a,
                                         uint32_t b0, uint32_t b1) {
    asm volatile(
        "mma.sync.aligned.m16n8k16.row.col.f32.bf16.bf16.f32 "
        "{%0,%1,%2,%3}, {%4,%5,%6,%7}, {%8,%9}, {%0,%1,%2,%3};"
        : "+f"(c[0]), "+f"(c[1]), "+f"(c[2]), "+f"(c[3])
        : "r"(a[0]), "r"(a[1]), "r"(a[2]), "r"(a[3]), "r"(b0), "r"(b1));
}

// ---------------- conv1: normalize + conv + relu -> bf16 hi/lo [ih][iw][ci] ----
__global__ void conv1_kernel(const float* __restrict__ x,
                             const float* __restrict__ mean,
                             const float* __restrict__ stdv,
                             const float* __restrict__ w,
                             const float* __restrict__ bias) {
    int oh = blockIdx.x, b = blockIdx.y;
    __shared__ float s_x[32 * 161];
    __shared__ float s_w[2048];
    __shared__ __nv_bfloat16 s_oh[2560], s_ol[2560];
    int tid = threadIdx.x;
    for (int i = tid; i < 32 * 161; i += 256) {
        int kh = i / 161, iw = i % 161;
        int ih = 2 * oh + kh;
        s_x[i] = (x[(b * 512 + ih) * 161 + iw] - mean[iw]) / stdv[iw];
    }
    for (int i = tid; i < 2048; i += 256) s_w[i] = w[i];
    __syncthreads();

    int c = tid >> 3, owb = tid & 7;
    float acc[10];
#pragma unroll
    for (int j = 0; j < 10; j++) acc[j] = 0.f;
    for (int kh = 0; kh < 32; kh++) {
        float w0 = s_w[c * 64 + kh * 2], w1 = s_w[c * 64 + kh * 2 + 1];
        const float* xr = &s_x[kh * 161];
#pragma unroll
        for (int j = 0; j < 10; j++) {
            int ow = owb + 8 * j;
            acc[j] += w0 * xr[2 * ow] + w1 * xr[2 * ow + 1];
        }
    }
    float bb = bias[c];
#pragma unroll
    for (int j = 0; j < 10; j++) {
        int ow = owb + 8 * j;
        float v = acc[j] + bb;
        v = v > 0.f ? v : 0.f;
        __nv_bfloat16 h = __float2bfloat16(v);
        s_oh[ow * 32 + c] = h;
        s_ol[ow * 32 + c] = __float2bfloat16(v - __bfloat162float(h));
    }
    __syncthreads();
    size_t base = (size_t)(b * C1H + oh) * 2560;
    const uint4* sh = (const uint4*)s_oh;
    const uint4* sl = (const uint4*)s_ol;
    uint4* dh = (uint4*)&g_c1h[base];
    uint4* dl = (uint4*)&g_c1l[base];
    for (int i = tid; i < 320; i += 256) { dh[i] = sh[i]; dl[i] = sl[i]; }
}

// -------- prep conv2 weights: split hi/lo bf16, layout [kh][kw][co][ci] --------
__global__ void prep_w2(const float* __restrict__ w) {
    int i = blockIdx.x * 256 + threadIdx.x;
    if (i >= 294912) return;
    int ci = i & 31;
    int co = (i >> 5) & 31;
    int kw = (i >> 10) % 9;
    int kh = i / 9216;
    float val = w[((co * 32 + ci) * 32 + kh) * 9 + kw];
    __nv_bfloat16 hi = __float2bfloat16(val);
    g_w2h[i] = hi;
    g_w2l[i] = __float2bfloat16(val - __bfloat162float(hi));
}

// ---------------- conv2 via mma.sync, shifted-window implicit GEMM -------------
// grid (35, 64), 384 threads. CTA = (b, 3 oh rows => M=108 pad 128), N=32 co.
// K per (kh,kw) = 32 ci. A rows are per-lane-addressed ldmatrix views into raw
// conv1 rows (stride 80B padded), so no im2col materialization.
__global__ void __launch_bounds__(384) conv2_mma_kernel(const float* __restrict__ bias) {
    extern __shared__ __align__(16) char base[];
    const int XH = 0, XL = 19200, BH = 38400, BL = 61440;   // bytes
    uint32_t sb = smem_u32(base);
    int tid = threadIdx.x, wid = tid >> 5, lane = tid & 31;
    int oh0 = blockIdx.x * 3, b = blockIdx.y;
    const __nv_bfloat16* c1h = g_c1h + (size_t)b * C1H * 2560;
    const __nv_bfloat16* c1l = g_c1l + (size_t)b * C1H * 2560;

    float acc[4][4];
#pragma unroll
    for (int i = 0; i < 4; i++)
#pragma unroll
        for (int j = 0; j < 4; j++) acc[i][j] = 0.f;

    int r = lane & 7, q = lane >> 3;
    int p = 16 * (wid & 7) + (q & 1) * 8 + r;
    if (p > 107) p = 107;
    int pohi = p / 36, pow_ = p - 36 * pohi;
    uint32_t a_base = (uint32_t)((pohi * 80 + 2 * pow_) * 80) + (q >> 1) * 16;
    uint32_t b_base = (uint32_t)(((q >> 1) * 8 + r) * 80) + (q & 1) * 16;

    for (int kh = 0; kh < 32; kh++) {
        int ihb = 2 * oh0 + kh;
        // stage A: 240 iw-rows (3 ohi x 80 iw) x 32 ci, dest stride 80B
        for (int i = tid; i < 960; i += 384) {
            int R = i >> 2, c8 = i & 3;
            int ohi2 = R / 80, iw = R - 80 * ohi2;
            size_t src = ((size_t)(ihb + 2 * ohi2) * 80 + iw) * 32 + c8 * 8;
            int dst = R * 80 + c8 * 16;
            *(uint4*)(base + XH + dst) = *(const uint4*)(c1h + src);
            *(uint4*)(base + XL + dst) = *(const uint4*)(c1l + src);
        }
        // stage B: 288 rows (9 kw x 32 co) x 32 ci, dest stride 80B
        for (int i = tid; i < 1152; i += 384) {
            int R = i >> 2, c8 = i & 3;
            size_t src = ((size_t)kh * 288 + R) * 32 + c8 * 8;
            int dst = R * 80 + c8 * 16;
            *(uint4*)(base + BH + dst) = *(const uint4*)(g_w2h + src);
            *(uint4*)(base + BL + dst) = *(const uint4*)(g_w2l + src);
        }
        __syncthreads();

        if (wid < 8) {
#pragma unroll 3
            for (int kw = 0; kw < 9; kw++) {
                uint32_t akw = a_base + (uint32_t)kw * 80;
                uint32_t bkw = b_base + (uint32_t)kw * 2560;
#pragma unroll
                for (int kc = 0; kc < 2; kc++) {
                    uint32_t ah[4], al[4];
                    ldsm4(ah, sb + XH + akw + kc * 32);
                    ldsm4(al, sb + XL + akw + kc * 32);
#pragma unroll
                    for (int np = 0; np < 2; np++) {
                        uint32_t bh[4], bl[4];
                        uint32_t ba = bkw + (uint32_t)np * 1280 + kc * 32;
                        ldsm4(bh, sb + BH + ba);
                        ldsm4(bl, sb + BL + ba);
                        mma_bf16(acc[2 * np],     ah, bh[0], bh[1]);
                        mma_bf16(acc[2 * np + 1], ah, bh[2], bh[3]);
                        mma_bf16(acc[2 * np],     ah, bl[0], bl[1]);
                        mma_bf16(acc[2 * np + 1], ah, bl[2], bl[3]);
                        mma_bf16(acc[2 * np],     al, bh[0], bh[1]);
                        mma_bf16(acc[2 * np + 1], al, bh[2], bh[3]);
                    }
                }
            }
        }
        __syncthreads();
    }

    // epilogue: fragment -> g_conv2 (b, t, co*36+ow), +bias, relu
    if (wid < 8) {
        int row0 = 16 * wid + (lane >> 2);
#pragma unroll
        for (int nt = 0; nt < 4; nt++) {
            int col = 8 * nt + (lane & 3) * 2;
            float b0 = bias[col], b1 = bias[col + 1];
#pragma unroll
            for (int h = 0; h < 2; h++) {
                int row = row0 + 8 * h;
                if (row < 108) {
                    int ohi = row / 36, ow = row - 36 * ohi;
                    float* dst = &g_conv2[((size_t)b * C2H + oh0 + ohi) * 1152 + ow];
                    float v0 = acc[nt][2 * h] + b0;
                    float v1 = acc[nt][2 * h + 1] + b1;
                    dst[col * 36] = v0 > 0.f ? v0 : 0.f;
                    dst[(col + 1) * 36] = v1 > 0.f ? v1 : 0.f;
                }
            }
        }
    }
}

// ---------------- generic C[M,N] = A[M,K] * B[N,K]^T + bias ----------------
__global__ void gemm_nt(const float* __restrict__ A, const float* __restrict__ Bm,
                        const float* __restrict__ bias, float* __restrict__ C,
                        int M, int N, int K) {
    __shared__ float sA[8][128];
    __shared__ float sB[8][128];
    int bm = blockIdx.y * 128, bn = blockIdx.x * 128;
    int tid = threadIdx.x;
    int ty = tid >> 4, tx = tid & 15;
    float acc[8][8];
#pragma unroll
    for (int i = 0; i < 8; i++)
#pragma unroll
        for (int j = 0; j < 8; j++) acc[i][j] = 0.f;

    int lrow = tid >> 1, lk = (tid & 1) * 4;
    for (int k0 = 0; k0 < K; k0 += 8) {
        float4 av = make_float4(0.f, 0.f, 0.f, 0.f);
        float4 bv = make_float4(0.f, 0.f, 0.f, 0.f);
        if (bm + lrow < M) av = *(const float4*)&A[(size_t)(bm + lrow) * K + k0 + lk];
        if (bn + lrow < N) bv = *(const float4*)&Bm[(size_t)(bn + lrow) * K + k0 + lk];
        sA[lk + 0][lrow] = av.x; sA[lk + 1][lrow] = av.y;
        sA[lk + 2][lrow] = av.z; sA[lk + 3][lrow] = av.w;
        sB[lk + 0][lrow] = bv.x; sB[lk + 1][lrow] = bv.y;
        sB[lk + 2][lrow] = bv.z; sB[lk + 3][lrow] = bv.w;
        __syncthreads();
#pragma unroll
        for (int k = 0; k < 8; k++) {
            float a[8], bb[8];
            *(float4*)&a[0] = *(const float4*)&sA[k][ty * 8];
            *(float4*)&a[4] = *(const float4*)&sA[k][ty * 8 + 4];
            *(float4*)&bb[0] = *(const float4*)&sB[k][tx * 8];
            *(float4*)&bb[4] = *(const float4*)&sB[k][tx * 8 + 4];
#pragma unroll
            for (int i = 0; i < 8; i++)
#pragma unroll
                for (int j = 0; j < 8; j++) acc[i][j] += a[i] * bb[j];
        }
        __syncthreads();
    }
    for (int i = 0; i < 8; i++) {
        int m = bm + ty * 8 + i;
        if (m >= M) break;
        for (int j = 0; j < 8; j++) {
            int n = bn + tx * 8 + j;
            if (n < N) C[(size_t)m * N + n] = acc[i][j] + bias[n];
        }
    }
}

// ---------------- encoder GRU: one block per batch element ----------------
__global__ void encoder_kernel(const float* __restrict__ w_hh,
                               const float* __restrict__ b_hh) {
    extern __shared__ float sm[];
    float* s_w = sm;              // 384*132 (padded stride)
    float* s_h = sm + 50688;
    float* s_gh = sm + 50816;
    int b = blockIdx.x, tid = threadIdx.x;
    for (int i = tid; i < 49152; i += 384) {
        int r = i >> 7, c = i & 127;
        s_w[r * 132 + c] = w_hh[i];
    }
    if (tid < 128) s_h[tid] = 0.f;
    __syncthreads();
    float bn = b_hh[tid];
    const float4* wr = (const float4*)&s_w[tid * 132];
    for (int t = 0; t < 105; t++) {
        float a0 = bn, a1 = 0.f;
#pragma unroll
        for (int k = 0; k < 16; k++) {
            float4 wv = wr[2 * k];
            float4 hv = ((const float4*)s_h)[2 * k];
            a0 += wv.x * hv.x + wv.y * hv.y + wv.z * hv.z + wv.w * hv.w;
            float4 wv2 = wr[2 * k + 1];
            float4 hv2 = ((const float4*)s_h)[2 * k + 1];
            a1 += wv2.x * hv2.x + wv2.y * hv2.y + wv2.z * hv2.z + wv2.w * hv2.w;
        }
        s_gh[tid] = a0 + a1;
        __syncthreads();
        if (tid < 128) {
            const float* xrow = &g_xp[((size_t)b * 105 + t) * 384];
            float r = 1.f / (1.f + __expf(-(xrow[tid] + s_gh[tid])));
            float z = 1.f / (1.f + __expf(-(xrow[128 + tid] + s_gh[128 + tid])));
            float nn = tanhf(xrow[256 + tid] + r * s_gh[256 + tid]);
            float hnew = (1.f - z) * nn + z * s_h[tid];
            s_h[tid] = hnew;
            g_eh[((size_t)b * 105 + t) * 128 + tid] = hnew;
        }
        __syncthreads();
    }
}

// ---------------- decoder: GRU step + attention, one block per batch ----------------
__device__ __forceinline__ float warpred_max(float v) {
#pragma unroll
    for (int o = 16; o; o >>= 1) v = fmaxf(v, __shfl_xor_sync(0xffffffffu, v, o));
    return v;
}
__device__ __forceinline__ float warpred_sum(float v) {
#pragma unroll
    for (int o = 16; o; o >>= 1) v += __shfl_xor_sync(0xffffffffu, v, o);
    return v;
}

__global__ void decoder_kernel(const float* __restrict__ b_hh) {
    extern __shared__ float sm[];
    float* s_eh = sm;              // 105*132
    float* s_h = sm + 13860;
    float* s_gh = sm + 13988;
    float* s_hx2 = sm + 14372;
    float* s_att = sm + 14500;
    float* s_red = sm + 14628;
    int b = blockIdx.x, tid = threadIdx.x;

    for (int i = tid; i < 13440; i += 384) {
        int t = i >> 7, k = i & 127;
        s_eh[t * 132 + k] = g_eh[(size_t)b * 105 * 128 + i];
    }
    if (tid < 128) s_h[tid] = 0.f;
    __syncthreads();

    float bn = b_hh[tid];
    for (int l = 0; l < 63; l++) {
        float a0 = bn, a1 = 0.f;
#pragma unroll 8
        for (int k = 0; k < 64; k++) {
            a0 += g_wT[k * 384 + tid] * s_h[k];
            a1 += g_wT[(k + 64) * 384 + tid] * s_h[k + 64];
        }
        s_gh[tid] = a0 + a1;
        __syncthreads();

        if (tid < 128) {
            const float* irow = &g_ip[((size_t)b * 63 + l) * 384];
            float r = 1.f / (1.f + __expf(-(irow[tid] + s_gh[tid])));
            float z = 1.f / (1.f + __expf(-(irow[128 + tid] + s_gh[128 + tid])));
            float nn = tanhf(irow[256 + tid] + r * s_gh[256 + tid]);
            s_hx2[tid] = (1.f - z) * nn + z * s_h[tid];
        }
        __syncthreads();

        float sc = -1e30f;
        if (tid < 105) {
            const float4* er = (const float4*)&s_eh[tid * 132];
            const float4* hx = (const float4*)s_hx2;
            float d = 0.f;
#pragma unroll 8
            for (int k = 0; k < 32; k++) {
                float4 e4 = er[k], h4 = hx[k];
                d += e4.x * h4.x + e4.y * h4.y + e4.z * h4.z + e4.w * h4.w;
            }
            sc = d;
        }
        float m = warpred_max(sc);
        if ((tid & 31) == 0) s_red[tid >> 5] = m;
        __syncthreads();
        if (tid < 32) {
            float wv = (tid < 12) ? s_red[tid] : -1e30f;
            wv = warpred_max(wv);
            if (tid == 0) s_red[12] = wv;
        }
        __syncthreads();
        float mx = s_red[12];
        float e = (tid < 105) ? __expf(sc - mx) : 0.f;
        float sv = warpred_sum(e);
        if ((tid & 31) == 0) s_red[16 + (tid >> 5)] = sv;
        if (tid < 128) s_att[tid] = e;
        __syncthreads();
        if (tid < 32) {
            float wv = (tid < 12) ? s_red[16 + tid] : 0.f;
            wv = warpred_sum(wv);
            if (tid == 0) s_red[13] = wv;
        }
        __syncthreads();
        float inv = 1.f / s_red[13];

        if (tid < 128) {
            float c = 0.f;
            for (int t = 0; t < 105; t++) c += s_att[t] * s_eh[t * 132 + tid];
            c *= inv;
            s_h[tid] = c;
            g_ctxs[((size_t)b * 63 + l) * 128 + tid] = c;
        }
        __syncthreads();
    }
}

// ---------------- small helpers ----------------
__global__ void emb_gather(const int* __restrict__ y, const float* __restrict__ emb) {
    int i = blockIdx.x * 256 + threadIdx.x;
    if (i >= NB * 63 * 32) return;
    int m = i >> 5, e = i & 31;
    int bb = m / 63, l = m % 63;
    int idx = y[bb * 64 + l];
    g_embA[i] = emb[idx * 32 + e];
}

__global__ void transpose_whh(const float* __restrict__ w) {
    int i = blockIdx.x * 256 + threadIdx.x;
    if (i < 49152) {
        int n = i >> 7, k = i & 127;
        g_wT[k * 384 + n] = w[i];
    }
}

// ---------------- launch ----------------
extern "C" void kernel_launch(void* const* d_in, const int* in_sizes, int n_in,
                              void* d_out, int out_size) {
    const float* x    = (const float*)d_in[0];
    const int*   y    = (const int*)d_in[1];
    const float* mean = (const float*)d_in[2];
    const float* stdv = (const float*)d_in[3];
    const float* c1w  = (const float*)d_in[4];
    const float* c1b  = (const float*)d_in[5];
    const float* c2w  = (const float*)d_in[6];
    const float* c2b  = (const float*)d_in[7];
    const float* gwih = (const float*)d_in[8];
    const float* gwhh = (const float*)d_in[9];
    const float* gbih = (const float*)d_in[10];
    const float* gbhh = (const float*)d_in[11];
    const float* emb  = (const float*)d_in[12];
    const float* dwih = (const float*)d_in[13];
    const float* dwhh = (const float*)d_in[14];
    const float* dbih = (const float*)d_in[15];
    const float* dbhh = (const float*)d_in[16];
    const float* fcw  = (const float*)d_in[17];
    const float* fcb  = (const float*)d_in[18];
    float* out = (float*)d_out;

    cudaFuncSetAttribute(encoder_kernel, cudaFuncAttributeMaxDynamicSharedMemorySize, 204800);
    cudaFuncSetAttribute(decoder_kernel, cudaFuncAttributeMaxDynamicSharedMemorySize, 58640);
    cudaFuncSetAttribute(conv2_mma_kernel, cudaFuncAttributeMaxDynamicSharedMemorySize, 84480);

    void *p_conv2, *p_xp, *p_embA, *p_ip, *p_ctxs;
    cudaGetSymbolAddress(&p_conv2, g_conv2);
    cudaGetSymbolAddress(&p_xp, g_xp);
    cudaGetSymbolAddress(&p_embA, g_embA);
    cudaGetSymbolAddress(&p_ip, g_ip);
    cudaGetSymbolAddress(&p_ctxs, g_ctxs);

    prep_w2<<<(294912 + 255) / 256, 256>>>(c2w);
    transpose_whh<<<192, 256>>>(dwhh);
    conv1_kernel<<<dim3(C1H, NB), 256>>>(x, mean, stdv, c1w, c1b);
    conv2_mma_kernel<<<dim3(35, NB), 384, 84480>>>(c2b);
    // xp = conv_out @ gru_w_ih^T + gru_b_ih : (6720,1152)x(384,1152)
    gemm_nt<<<dim3(3, 53), 256>>>((const float*)p_conv2, gwih, gbih, (float*)p_xp,
                                  NB * C2H, 384, 1152);
    encoder_kernel<<<NB, 384, 204800>>>(gwhh, gbhh);

    emb_gather<<<(NB * 63 * 32 + 255) / 256, 256>>>(y, emb);
    // ip = emb_in @ dec_w_ih^T + dec_b_ih : (4032,32)x(384,32)
    gemm_nt<<<dim3(3, 32), 256>>>((const float*)p_embA, dwih, dbih, (float*)p_ip,
                                  NB * 63, 384, 32);
    decoder_kernel<<<NB, 384, 58640>>>(dbhh);
    // out = ctxs @ fc_w^T + fc_b : (4032,128)x(32,128)
    gemm_nt<<<dim3(1, 32), 256>>>((const float*)p_ctxs, fcw, fcb, out,
                                  NB * 63, 32, 128);
}

// round 12
// speedup vs baseline: 5.5450x; 1.1139x over previous
#include <cuda_runtime.h>
#include <cuda_bf16.h>
#include <math.h>
#include <stdint.h>

// Model dims: B=64,T=512,F=161,V=32,L=64,H=128,E=32
// conv1: (64,1,512,161)->(64,32,241,80)  conv2: ->(64,32,105,36) -> (64,105,1152)
#define NB 64
#define C1H 241
#define C1W 80
#define C2H 105

typedef unsigned long long ull;

// ---------------- device scratch ----------------
// conv1 output as bf16 hi/lo, layout [b][ih][iw][ci]
__device__ __nv_bfloat16 g_c1h[NB * C1H * C1W * 32];
__device__ __nv_bfloat16 g_c1l[NB * C1H * C1W * 32];
__device__ float g_conv2[NB * C2H * 1152];
__device__ float g_xp   [NB * C2H * 384];
__device__ float g_eh   [NB * C2H * 128];
__device__ float g_embA [NB * 63 * 32];
__device__ float g_ip   [NB * 63 * 384];
__device__ float g_ctxs [NB * 63 * 128];
__device__ float g_wT   [128 * 384];
// conv2 weight B-fragments pre-packed per mma lane:
// index (((kh*9+kw)*2+kc)*2+np)*32+lane -> uint4 = (b0,b1) for co-tiles (lo8, hi8)
__device__ uint4 g_wfh[36864];
__device__ uint4 g_wfl[36864];

// ---------------- helpers ----------------
__device__ __forceinline__ uint32_t smem_u32(const void* p) {
    uint32_t a;
    asm("{ .reg .u64 t; cvta.to.shared.u64 t, %1; cvt.u32.u64 %0, t; }" : "=r"(a) : "l"(p));
    return a;
}
__device__ __forceinline__ void ldsm4(uint32_t* d, uint32_t addr) {
    asm volatile("ldmatrix.sync.aligned.m8n8.x4.shared.b16 {%0,%1,%2,%3}, [%4];"
                 : "=r"(d[0]), "=r"(d[1]), "=r"(d[2]), "=r"(d[3]) : "r"(addr));
}
__device__ __forceinline__ void mma_bf16(float* c, const uint32_t* a,
                                         uint32_t b0, uint32_t b1) {
    asm volatile(
        "mma.sync.aligned.m16n8k16.row.col.f32.bf16.bf16.f32 "
        "{%0,%1,%2,%3}, {%4,%5,%6,%7}, {%8,%9}, {%0,%1,%2,%3};"
        : "+f"(c[0]), "+f"(c[1]), "+f"(c[2]), "+f"(c[3])
        : "r"(a[0]), "r"(a[1]), "r"(a[2]), "r"(a[3]), "r"(b0), "r"(b1));
}
__device__ __forceinline__ void cpa16(uint32_t dst, const void* src) {
    asm volatile("cp.async.cg.shared.global [%0], [%1], 16;" :: "r"(dst), "l"(src));
}
__device__ __forceinline__ uint32_t pack_bf2(float x, float y) {
    __nv_bfloat16 h0 = __float2bfloat16(x), h1 = __float2bfloat16(y);
    return ((uint32_t)__bfloat16_as_ushort(h1) << 16) | (uint32_t)__bfloat16_as_ushort(h0);
}

// ---------------- conv1: normalize + conv + relu -> bf16 hi/lo [ih][iw][ci] ----
__global__ void conv1_kernel(const float* __restrict__ x,
                             const float* __restrict__ mean,
                             const float* __restrict__ stdv,
                             const float* __restrict__ w,
                             const float* __restrict__ bias) {
    int oh = blockIdx.x, b = blockIdx.y;
    __shared__ float s_x[32 * 161];
    __shared__ float s_w[2048];
    __shared__ __nv_bfloat16 s_oh[2560], s_ol[2560];
    int tid = threadIdx.x;
    for (int i = tid; i < 32 * 161; i += 256) {
        int kh = i / 161, iw = i % 161;
        int ih = 2 * oh + kh;
        s_x[i] = (x[(b * 512 + ih) * 161 + iw] - mean[iw]) / stdv[iw];
    }
    for (int i = tid; i < 2048; i += 256) s_w[i] = w[i];
    __syncthreads();

    int c = tid >> 3, owb = tid & 7;
    float acc[10];
#pragma unroll
    for (int j = 0; j < 10; j++) acc[j] = 0.f;
    for (int kh = 0; kh < 32; kh++) {
        float w0 = s_w[c * 64 + kh * 2], w1 = s_w[c * 64 + kh * 2 + 1];
        const float* xr = &s_x[kh * 161];
#pragma unroll
        for (int j = 0; j < 10; j++) {
            int ow = owb + 8 * j;
            acc[j] += w0 * xr[2 * ow] + w1 * xr[2 * ow + 1];
        }
    }
    float bb = bias[c];
#pragma unroll
    for (int j = 0; j < 10; j++) {
        int ow = owb + 8 * j;
        float v = acc[j] + bb;
        v = v > 0.f ? v : 0.f;
        __nv_bfloat16 h = __float2bfloat16(v);
        s_oh[ow * 32 + c] = h;
        s_ol[ow * 32 + c] = __float2bfloat16(v - __bfloat162float(h));
    }
    __syncthreads();
    size_t base = (size_t)(b * C1H + oh) * 2560;
    const uint4* sh = (const uint4*)s_oh;
    const uint4* sl = (const uint4*)s_ol;
    uint4* dh = (uint4*)&g_c1h[base];
    uint4* dl = (uint4*)&g_c1l[base];
    for (int i = tid; i < 320; i += 256) { dh[i] = sh[i]; dl[i] = sl[i]; }
}

// -------- prep conv2 weight B-fragments (hi/lo), one uint4 pair per thread -----
__global__ void prep_wf(const float* __restrict__ w) {
    int i = blockIdx.x * 256 + threadIdx.x;
    if (i >= 36864) return;
    int lane = i & 31; int t = i >> 5;
    int np = t & 1; t >>= 1;
    int kc = t & 1; t >>= 1;
    int kw = t % 9; int kh = t / 9;
    int co0 = np * 16 + (lane >> 2);
    int ci0 = kc * 16 + 2 * (lane & 3);
    uint32_t rh[4], rl[4];
#pragma unroll
    for (int j = 0; j < 4; j++) {
        int co = co0 + (j >> 1) * 8;
        int ci = ci0 + (j & 1) * 8;
        float v0 = w[((co * 32 + ci) * 32 + kh) * 9 + kw];
        float v1 = w[((co * 32 + ci + 1) * 32 + kh) * 9 + kw];
        __nv_bfloat16 h0 = __float2bfloat16(v0), h1 = __float2bfloat16(v1);
        rh[j] = ((uint32_t)__bfloat16_as_ushort(h1) << 16)
              | (uint32_t)__bfloat16_as_ushort(h0);
        rl[j] = pack_bf2(v0 - __bfloat162float(h0), v1 - __bfloat162float(h1));
    }
    g_wfh[i] = make_uint4(rh[0], rh[1], rh[2], rh[3]);
    g_wfl[i] = make_uint4(rl[0], rl[1], rl[2], rl[3]);
}

// ---------------- conv2 via mma.sync: shifted-window, B by LDG, A cp.async ----
// grid (35, 64), 384 threads. CTA = (b, 3 oh rows => M=108 pad 128), N=32 co.
// A double-buffered (38400B each); B fragments direct from L2.
__global__ void __launch_bounds__(384) conv2_mma_kernel(const float* __restrict__ bias) {
    extern __shared__ __align__(16) char base[];
    uint32_t sb = smem_u32(base);
    int tid = threadIdx.x, wid = tid >> 5, lane = tid & 31;
    int oh0 = blockIdx.x * 3, b = blockIdx.y;
    const __nv_bfloat16* c1h = g_c1h + (size_t)b * C1H * 2560;
    const __nv_bfloat16* c1l = g_c1l + (size_t)b * C1H * 2560;

    float acc[4][4];
#pragma unroll
    for (int i = 0; i < 4; i++)
#pragma unroll
        for (int j = 0; j < 4; j++) acc[i][j] = 0.f;

    int r = lane & 7, q = lane >> 3;
    int p = 16 * (wid & 7) + (q & 1) * 8 + r;
    if (p > 107) p = 107;
    int pohi = p / 36, pow_ = p - 36 * pohi;
    uint32_t a_base = (uint32_t)((pohi * 80 + 2 * pow_) * 80) + (q >> 1) * 16;

    // ---- stage A rows for one kh into buffer buf ----
    auto stage = [&](int kh, int buf) {
        uint32_t xh = sb + (uint32_t)buf * 38400u;
        uint32_t xl = xh + 19200u;
        int ihb = 2 * oh0 + kh;
        for (int i = tid; i < 960; i += 384) {
            int R = i >> 2, c8 = i & 3;
            int ohi2 = R / 80, iw = R - 80 * ohi2;
            size_t src = ((size_t)(ihb + 2 * ohi2) * 80 + iw) * 32 + c8 * 8;
            uint32_t d = (uint32_t)(R * 80 + c8 * 16);
            cpa16(xh + d, c1h + src);
            cpa16(xl + d, c1l + src);
        }
        asm volatile("cp.async.commit_group;" ::: "memory");
    };

    stage(0, 0);
    for (int kh = 0; kh < 32; kh++) {
        if (kh < 31) {
            stage(kh + 1, (kh + 1) & 1);
            asm volatile("cp.async.wait_group 1;" ::: "memory");
        } else {
            asm volatile("cp.async.wait_group 0;" ::: "memory");
        }
        __syncthreads();

        if (wid < 8) {
            uint32_t xh = sb + (uint32_t)(kh & 1) * 38400u;
            uint32_t xl = xh + 19200u;
            const uint4* wfh = g_wfh + (size_t)kh * 1152 + lane;
            const uint4* wfl = g_wfl + (size_t)kh * 1152 + lane;
#pragma unroll 3
            for (int kw = 0; kw < 9; kw++) {
                uint32_t akw = a_base + (uint32_t)kw * 80;
#pragma unroll
                for (int kc = 0; kc < 2; kc++) {
                    uint32_t ah[4], al[4];
                    ldsm4(ah, xh + akw + kc * 32);
                    ldsm4(al, xl + akw + kc * 32);
#pragma unroll
                    for (int np = 0; np < 2; np++) {
                        int fi = ((kw * 2 + kc) * 2 + np) * 32;
                        uint4 bh = wfh[fi];
                        uint4 bl = wfl[fi];
                        mma_bf16(acc[2 * np],     ah, bh.x, bh.y);
                        mma_bf16(acc[2 * np + 1], ah, bh.z, bh.w);
                        mma_bf16(acc[2 * np],     ah, bl.x, bl.y);
                        mma_bf16(acc[2 * np + 1], ah, bl.z, bl.w);
                        mma_bf16(acc[2 * np],     al, bh.x, bh.y);
                        mma_bf16(acc[2 * np + 1], al, bh.z, bh.w);
                    }
                }
            }
        }
        __syncthreads();
    }

    // epilogue: fragment -> g_conv2 (b, t, co*36+ow), +bias, relu
    if (wid < 8) {
        int row0 = 16 * wid + (lane >> 2);
#pragma unroll
        for (int nt = 0; nt < 4; nt++) {
            int col = 8 * nt + (lane & 3) * 2;
            float b0 = bias[col], b1 = bias[col + 1];
#pragma unroll
            for (int h = 0; h < 2; h++) {
                int row = row0 + 8 * h;
                if (row < 108) {
                    int ohi = row / 36, ow = row - 36 * ohi;
                    float* dst = &g_conv2[((size_t)b * C2H + oh0 + ohi) * 1152 + ow];
                    float v0 = acc[nt][2 * h] + b0;
                    float v1 = acc[nt][2 * h + 1] + b1;
                    dst[col * 36] = v0 > 0.f ? v0 : 0.f;
                    dst[(col + 1) * 36] = v1 > 0.f ? v1 : 0.f;
                }
            }
        }
    }
}

// ---------------- generic C[M,N] = A[M,K] * B[N,K]^T + bias ----------------
__global__ void gemm_nt(const float* __restrict__ A, const float* __restrict__ Bm,
                        const float* __restrict__ bias, float* __restrict__ C,
                        int M, int N, int K) {
    __shared__ float sA[8][128];
    __shared__ float sB[8][128];
    int bm = blockIdx.y * 128, bn = blockIdx.x * 128;
    int tid = threadIdx.x;
    int ty = tid >> 4, tx = tid & 15;
    float acc[8][8];
#pragma unroll
    for (int i = 0; i < 8; i++)
#pragma unroll
        for (int j = 0; j < 8; j++) acc[i][j] = 0.f;

    int lrow = tid >> 1, lk = (tid & 1) * 4;
    for (int k0 = 0; k0 < K; k0 += 8) {
        float4 av = make_float4(0.f, 0.f, 0.f, 0.f);
        float4 bv = make_float4(0.f, 0.f, 0.f, 0.f);
        if (bm + lrow < M) av = *(const float4*)&A[(size_t)(bm + lrow) * K + k0 + lk];
        if (bn + lrow < N) bv = *(const float4*)&Bm[(size_t)(bn + lrow) * K + k0 + lk];
        sA[lk + 0][lrow] = av.x; sA[lk + 1][lrow] = av.y;
        sA[lk + 2][lrow] = av.z; sA[lk + 3][lrow] = av.w;
        sB[lk + 0][lrow] = bv.x; sB[lk + 1][lrow] = bv.y;
        sB[lk + 2][lrow] = bv.z; sB[lk + 3][lrow] = bv.w;
        __syncthreads();
#pragma unroll
        for (int k = 0; k < 8; k++) {
            float a[8], bb[8];
            *(float4*)&a[0] = *(const float4*)&sA[k][ty * 8];
            *(float4*)&a[4] = *(const float4*)&sA[k][ty * 8 + 4];
            *(float4*)&bb[0] = *(const float4*)&sB[k][tx * 8];
            *(float4*)&bb[4] = *(const float4*)&sB[k][tx * 8 + 4];
#pragma unroll
            for (int i = 0; i < 8; i++)
#pragma unroll
                for (int j = 0; j < 8; j++) acc[i][j] += a[i] * bb[j];
        }
        __syncthreads();
    }
    for (int i = 0; i < 8; i++) {
        int m = bm + ty * 8 + i;
        if (m >= M) break;
        for (int j = 0; j < 8; j++) {
            int n = bn + tx * 8 + j;
            if (n < N) C[(size_t)m * N + n] = acc[i][j] + bias[n];
        }
    }
}

// ---------------- encoder GRU: one block per batch element ----------------
__global__ void encoder_kernel(const float* __restrict__ w_hh,
                               const float* __restrict__ b_hh) {
    extern __shared__ float sm[];
    float* s_w = sm;              // 384*132 (padded stride)
    float* s_h = sm + 50688;
    float* s_gh = sm + 50816;
    int b = blockIdx.x, tid = threadIdx.x;
    for (int i = tid; i < 49152; i += 384) {
        int r = i >> 7, c = i & 127;
        s_w[r * 132 + c] = w_hh[i];
    }
    if (tid < 128) s_h[tid] = 0.f;
    __syncthreads();
    float bn = b_hh[tid];
    const float4* wr = (const float4*)&s_w[tid * 132];
    for (int t = 0; t < 105; t++) {
        float a0 = bn, a1 = 0.f;
#pragma unroll
        for (int k = 0; k < 16; k++) {
            float4 wv = wr[2 * k];
            float4 hv = ((const float4*)s_h)[2 * k];
            a0 += wv.x * hv.x + wv.y * hv.y + wv.z * hv.z + wv.w * hv.w;
            float4 wv2 = wr[2 * k + 1];
            float4 hv2 = ((const float4*)s_h)[2 * k + 1];
            a1 += wv2.x * hv2.x + wv2.y * hv2.y + wv2.z * hv2.z + wv2.w * hv2.w;
        }
        s_gh[tid] = a0 + a1;
        __syncthreads();
        if (tid < 128) {
            const float* xrow = &g_xp[((size_t)b * 105 + t) * 384];
            float r = 1.f / (1.f + __expf(-(xrow[tid] + s_gh[tid])));
            float z = 1.f / (1.f + __expf(-(xrow[128 + tid] + s_gh[128 + tid])));
            float nn = tanhf(xrow[256 + tid] + r * s_gh[256 + tid]);
            float hnew = (1.f - z) * nn + z * s_h[tid];
            s_h[tid] = hnew;
            g_eh[((size_t)b * 105 + t) * 128 + tid] = hnew;
        }
        __syncthreads();
    }
}

// ---------------- decoder: GRU step + attention, one block per batch ----------------
__device__ __forceinline__ float warpred_max(float v) {
#pragma unroll
    for (int o = 16; o; o >>= 1) v = fmaxf(v, __shfl_xor_sync(0xffffffffu, v, o));
    return v;
}
__device__ __forceinline__ float warpred_sum(float v) {
#pragma unroll
    for (int o = 16; o; o >>= 1) v += __shfl_xor_sync(0xffffffffu, v, o);
    return v;
}

__global__ void decoder_kernel(const float* __restrict__ b_hh) {
    extern __shared__ float sm[];
    float* s_eh = sm;              // 105*132
    float* s_h = sm + 13860;
    float* s_gh = sm + 13988;
    float* s_hx2 = sm + 14372;
    float* s_att = sm + 14500;
    float* s_red = sm + 14628;
    int b = blockIdx.x, tid = threadIdx.x;

    for (int i = tid; i < 13440; i += 384) {
        int t = i >> 7, k = i & 127;
        s_eh[t * 132 + k] = g_eh[(size_t)b * 105 * 128 + i];
    }
    if (tid < 128) s_h[tid] = 0.f;
    __syncthreads();

    float bn = b_hh[tid];
    for (int l = 0; l < 63; l++) {
        float a0 = bn, a1 = 0.f;
#pragma unroll 8
        for (int k = 0; k < 64; k++) {
            a0 += g_wT[k * 384 + tid] * s_h[k];
            a1 += g_wT[(k + 64) * 384 + tid] * s_h[k + 64];
        }
        s_gh[tid] = a0 + a1;
        __syncthreads();

        if (tid < 128) {
            const float* irow = &g_ip[((size_t)b * 63 + l) * 384];
            float r = 1.f / (1.f + __expf(-(irow[tid] + s_gh[tid])));
            float z = 1.f / (1.f + __expf(-(irow[128 + tid] + s_gh[128 + tid])));
            float nn = tanhf(irow[256 + tid] + r * s_gh[256 + tid]);
            s_hx2[tid] = (1.f - z) * nn + z * s_h[tid];
        }
        __syncthreads();

        float sc = -1e30f;
        if (tid < 105) {
            const float4* er = (const float4*)&s_eh[tid * 132];
            const float4* hx = (const float4*)s_hx2;
            float d = 0.f;
#pragma unroll 8
            for (int k = 0; k < 32; k++) {
                float4 e4 = er[k], h4 = hx[k];
                d += e4.x * h4.x + e4.y * h4.y + e4.z * h4.z + e4.w * h4.w;
            }
            sc = d;
        }
        float m = warpred_max(sc);
        if ((tid & 31) == 0) s_red[tid >> 5] = m;
        __syncthreads();
        if (tid < 32) {
            float wv = (tid < 12) ? s_red[tid] : -1e30f;
            wv = warpred_max(wv);
            if (tid == 0) s_red[12] = wv;
        }
        __syncthreads();
        float mx = s_red[12];
        float e = (tid < 105) ? __expf(sc - mx) : 0.f;
        float sv = warpred_sum(e);
        if ((tid & 31) == 0) s_red[16 + (tid >> 5)] = sv;
        if (tid < 128) s_att[tid] = e;
        __syncthreads();
        if (tid < 32) {
            float wv = (tid < 12) ? s_red[16 + tid] : 0.f;
            wv = warpred_sum(wv);
            if (tid == 0) s_red[13] = wv;
        }
        __syncthreads();
        float inv = 1.f / s_red[13];

        if (tid < 128) {
            float c = 0.f;
            for (int t = 0; t < 105; t++) c += s_att[t] * s_eh[t * 132 + tid];
            c *= inv;
            s_h[tid] = c;
            g_ctxs[((size_t)b * 63 + l) * 128 + tid] = c;
        }
        __syncthreads();
    }
}

// ---------------- small helpers ----------------
__global__ void emb_gather(const int* __restrict__ y, const float* __restrict__ emb) {
    int i = blockIdx.x * 256 + threadIdx.x;
    if (i >= NB * 63 * 32) return;
    int m = i >> 5, e = i & 31;
    int bb = m / 63, l = m % 63;
    int idx = y[bb * 64 + l];
    g_embA[i] = emb[idx * 32 + e];
}

__global__ void transpose_whh(const float* __restrict__ w) {
    int i = blockIdx.x * 256 + threadIdx.x;
    if (i < 49152) {
        int n = i >> 7, k = i & 127;
        g_wT[k * 384 + n] = w[i];
    }
}

// ---------------- launch ----------------
extern "C" void kernel_launch(void* const* d_in, const int* in_sizes, int n_in,
                              void* d_out, int out_size) {
    const float* x    = (const float*)d_in[0];
    const int*   y    = (const int*)d_in[1];
    const float* mean = (const float*)d_in[2];
    const float* stdv = (const float*)d_in[3];
    const float* c1w  = (const float*)d_in[4];
    const float* c1b  = (const float*)d_in[5];
    const float* c2w  = (const float*)d_in[6];
    const float* c2b  = (const float*)d_in[7];
    const float* gwih = (const float*)d_in[8];
    const float* gwhh = (const float*)d_in[9];
    const float* gbih = (const float*)d_in[10];
    const float* gbhh = (const float*)d_in[11];
    const float* emb  = (const float*)d_in[12];
    const float* dwih = (const float*)d_in[13];
    const float* dwhh = (const float*)d_in[14];
    const float* dbih = (const float*)d_in[15];
    const float* dbhh = (const float*)d_in[16];
    const float* fcw  = (const float*)d_in[17];
    const float* fcb  = (const float*)d_in[18];
    float* out = (float*)d_out;

    cudaFuncSetAttribute(encoder_kernel, cudaFuncAttributeMaxDynamicSharedMemorySize, 204800);
    cudaFuncSetAttribute(decoder_kernel, cudaFuncAttributeMaxDynamicSharedMemorySize, 58640);
    cudaFuncSetAttribute(conv2_mma_kernel, cudaFuncAttributeMaxDynamicSharedMemorySize, 76800);

    void *p_conv2, *p_xp, *p_embA, *p_ip, *p_ctxs;
    cudaGetSymbolAddress(&p_conv2, g_conv2);
    cudaGetSymbolAddress(&p_xp, g_xp);
    cudaGetSymbolAddress(&p_embA, g_embA);
    cudaGetSymbolAddress(&p_ip, g_ip);
    cudaGetSymbolAddress(&p_ctxs, g_ctxs);

    prep_wf<<<144, 256>>>(c2w);
    transpose_whh<<<192, 256>>>(dwhh);
    conv1_kernel<<<dim3(C1H, NB), 256>>>(x, mean, stdv, c1w, c1b);
    conv2_mma_kernel<<<dim3(35, NB), 384, 76800>>>(c2b);
    // xp = conv_out @ gru_w_ih^T + gru_b_ih : (6720,1152)x(384,1152)
    gemm_nt<<<dim3(3, 53), 256>>>((const float*)p_conv2, gwih, gbih, (float*)p_xp,
                                  NB * C2H, 384, 1152);
    encoder_kernel<<<NB, 384, 204800>>>(gwhh, gbhh);

    emb_gather<<<(NB * 63 * 32 + 255) / 256, 256>>>(y, emb);
    // ip = emb_in @ dec_w_ih^T + dec_b_ih : (4032,32)x(384,32)
    gemm_nt<<<dim3(3, 32), 256>>>((const float*)p_embA, dwih, dbih, (float*)p_ip,
                                  NB * 63, 384, 32);
    decoder_kernel<<<NB, 384, 58640>>>(dbhh);
    // out = ctxs @ fc_w^T + fc_b : (4032,128)x(32,128)
    gemm_nt<<<dim3(1, 32), 256>>>((const float*)p_ctxs, fcw, fcb, out,
                                  NB * 63, 32, 128);
}